// round 7
// baseline (speedup 1.0000x reference)
#include <cuda_runtime.h>
#include <cuda_fp16.h>
#include <stdint.h>

// Problem constants (fixed by the reference)
#define BATCH 1024
#define IN_SIZE 2048
#define OUT_SIZE 2048
#define EMAX 131072

#define BK 64                           // halves per K chunk (128B = SW128 row)
#define NCHUNKS (IN_SIZE / BK)          // 32
#define TILE_BYTES 16384                // 128 rows x 128 bytes
#define STAGE_BYTES (2 * TILE_BYTES)    // A tile + B tile
#define NSTAGES 3
#define SMEM_TOTAL (NSTAGES * STAGE_BYTES)   // 96 KB

// -------- device scratch (no allocations allowed) --------
__device__ __half g_Wh[OUT_SIZE * IN_SIZE];    // 8 MB dense weights fp16 [out][in]
__device__ __half g_xh[BATCH * IN_SIZE];       // 4 MB x fp16 [batch][in]
__device__ int    g_idx64;

__device__ __forceinline__ int fetch_idx(const void* p, int e, int is64) {
    if (is64) return (int)(((const long long*)p)[e]);
    return ((const int*)p)[e];
}

// ---------------- helpers ----------------
__device__ __forceinline__ uint32_t smem_u32(const void* p) {
    uint32_t a;
    asm("{ .reg .u64 t; cvta.to.shared.u64 t, %1; cvt.u32.u64 %0, t; }"
        : "=r"(a) : "l"(p));
    return a;
}
#define SWZ128(off) ((off) ^ (((off) >> 3) & 0x70))
#define CP_ASYNC16(dst, src) \
    asm volatile("cp.async.cg.shared.global [%0], [%1], 16;" :: "r"(dst), "l"(src))
#define CP_COMMIT() asm volatile("cp.async.commit_group;" ::: "memory")
#define CP_WAIT1()  asm volatile("cp.async.wait_group 1;" ::: "memory")
#define CP_WAIT0()  asm volatile("cp.async.wait_group 0;" ::: "memory")
#define LDSM4(r0, r1, r2, r3, a)                                               \
    asm volatile("ldmatrix.sync.aligned.m8n8.x4.shared.b16 {%0,%1,%2,%3}, [%4];" \
                 : "=r"(r0), "=r"(r1), "=r"(r2), "=r"(r3) : "r"(a))
#define MMA16816(c, a, b0, b1)                                                 \
    asm volatile(                                                              \
        "mma.sync.aligned.m16n8k16.row.col.f32.f16.f16.f32 "                   \
        "{%0,%1,%2,%3}, {%4,%5,%6,%7}, {%8,%9}, {%0,%1,%2,%3};"                \
        : "+f"(c[0]), "+f"(c[1]), "+f"(c[2]), "+f"(c[3])                       \
        : "r"(a[0]), "r"(a[1]), "r"(a[2]), "r"(a[3]), "r"(b0), "r"(b1))

// -------- 1. detect index dtype --------
__global__ void setup_kernel(const void* in_idx, int E) {
    int lane = threadIdx.x;
    const long long* q = (const long long*)in_idx;
    long long v = (lane < E) ? q[lane] : 0;
    bool bad = (v < 0 || v >= IN_SIZE);
    unsigned m = __ballot_sync(0xFFFFFFFFu, bad);
    if (lane == 0) g_idx64 = (m == 0) ? 1 : 0;
}

// -------- 2. zero Wh (every launch: graph replays) --------
__global__ void zero_w_kernel() {
    int t = blockIdx.x * blockDim.x + threadIdx.x;
    reinterpret_cast<uint4*>(g_Wh)[t] = make_uint4(0, 0, 0, 0);
}

// -------- 3. scatter-add weights into dense fp16 W (native f16x2 atomics) ---
__global__ void scatter_w_kernel(const void* in_idx, const void* out_idx,
                                 const float* w, int E) {
    int is64 = g_idx64;
    const __half zero = __float2half_rn(0.f);
    for (int e = blockIdx.x * blockDim.x + threadIdx.x; e < E;
         e += gridDim.x * blockDim.x) {
        int o = fetch_idx(out_idx, e, is64);
        int i = fetch_idx(in_idx, e, is64);
        int idx = o * IN_SIZE + i;
        __half hw = __float2half_rn(w[e]);
        __half2* p = reinterpret_cast<__half2*>(g_Wh + (idx & ~1));
        __half2 v = (idx & 1) ? __halves2half2(zero, hw)
                              : __halves2half2(hw, zero);
        atomicAdd(p, v);
    }
}

// -------- 4. convert x fp32 -> fp16 --------
__global__ void convert_x_kernel(const float* __restrict__ x) {
    int t = blockIdx.x * blockDim.x + threadIdx.x;
    float4 v = reinterpret_cast<const float4*>(x)[t];
    __half2 h0 = __floats2half2_rn(v.x, v.y);
    __half2 h1 = __floats2half2_rn(v.z, v.w);
    reinterpret_cast<__half2*>(g_xh)[2 * t]     = h0;
    reinterpret_cast<__half2*>(g_xh)[2 * t + 1] = h1;
}

// -------- 5. GEMM: out[b][o] = sum_k xh[b][k] * Wh[o][k] --------------------
// CTA tile M128 x N128, 8 warps in 2x4 (64x32 per warp), BK=64, 3-stage
// cp.async pipeline, ldmatrix + mma.sync.m16n8k16 (HMMA, fp32 accum).
__global__ void __launch_bounds__(256, 1) gemm_kernel(float* __restrict__ out) {
    extern __shared__ char smem[];
    uint32_t sb = smem_u32(smem);
    int t = threadIdx.x;
    int wid = t >> 5;
    int lane = t & 31;
    int m0 = blockIdx.y << 7;   // batch tile origin
    int n0 = blockIdx.x << 7;   // out tile origin
    int wm = (wid & 1) << 6;    // warp m-origin within tile (0/64)
    int wn = (wid >> 1) << 5;   // warp n-origin within tile (0/32/64/96)

    const __half* axh = g_xh + (size_t)m0 * IN_SIZE;
    const __half* bwh = g_Wh + (size_t)n0 * IN_SIZE;

    // stage loader: chunk kc -> stage s. 2048 x 16B over 256 threads.
    auto load_tile = [&](int kc, int s) {
        uint32_t stage = sb + s * STAGE_BYTES;
        const __half* as = axh + kc * BK;
        const __half* bs = bwh + kc * BK;
#pragma unroll
        for (int q = t; q < 2048; q += 256) {
            int tile = q >> 10;           // 0=A, 1=B
            int r = (q >> 3) & 127;
            int sg = q & 7;
            uint32_t dst = stage + tile * TILE_BYTES + SWZ128((r << 7) + (sg << 4));
            const __half* src = (tile ? bs : as) + (size_t)r * IN_SIZE + sg * 8;
            CP_ASYNC16(dst, src);
        }
        CP_COMMIT();
    };

    float c[4][4][4];
#pragma unroll
    for (int a = 0; a < 4; a++)
#pragma unroll
        for (int b = 0; b < 4; b++)
#pragma unroll
            for (int k = 0; k < 4; k++) c[a][b][k] = 0.f;

    load_tile(0, 0);
    load_tile(1, 1);

    // per-lane ldmatrix address components (within-tile, pre-swizzle)
    int a_row = wm + (lane & 15);           // + mi*16
    int a_kh = (lane >> 4) << 3;            // + kk
    int b_row = wn + (lane & 7) + ((lane >> 4) << 3);  // + nj*16
    int b_kh = ((lane >> 3) & 1) << 3;      // + kk

    for (int ch = 0; ch < NCHUNKS; ch++) {
        CP_WAIT1();
        __syncthreads();
        uint32_t sA = sb + (ch % NSTAGES) * STAGE_BYTES;
        uint32_t sB = sA + TILE_BYTES;
#pragma unroll
        for (int kk = 0; kk < BK; kk += 16) {
            uint32_t af[4][4], bf[2][4];
#pragma unroll
            for (int mi = 0; mi < 4; mi++) {
                uint32_t ad = sA + SWZ128(((a_row + (mi << 4)) << 7) +
                                          ((kk + a_kh) << 1));
                LDSM4(af[mi][0], af[mi][1], af[mi][2], af[mi][3], ad);
            }
#pragma unroll
            for (int nj = 0; nj < 2; nj++) {
                uint32_t bd = sB + SWZ128(((b_row + (nj << 4)) << 7) +
                                          ((kk + b_kh) << 1));
                LDSM4(bf[nj][0], bf[nj][1], bf[nj][2], bf[nj][3], bd);
            }
#pragma unroll
            for (int mi = 0; mi < 4; mi++)
#pragma unroll
                for (int j = 0; j < 4; j++)
                    MMA16816(c[mi][j], af[mi],
                             bf[j >> 1][(j & 1) << 1],
                             bf[j >> 1][((j & 1) << 1) + 1]);
        }
        __syncthreads();
        if (ch + 2 < NCHUNKS) load_tile(ch + 2, (ch + 2) % NSTAGES);
    }

    // epilogue: write fp32 accumulators straight to d_out
    int rbase = m0 + wm + (lane >> 2);
    int cbase = n0 + wn + ((lane & 3) << 1);
#pragma unroll
    for (int mi = 0; mi < 4; mi++) {
#pragma unroll
        for (int j = 0; j < 4; j++) {
            int row = rbase + (mi << 4);
            int col = cbase + (j << 3);
            float* p0 = out + (size_t)row * OUT_SIZE + col;
            float* p1 = out + (size_t)(row + 8) * OUT_SIZE + col;
            p0[0] = c[mi][j][0]; p0[1] = c[mi][j][1];
            p1[0] = c[mi][j][2]; p1[1] = c[mi][j][3];
        }
    }
}

extern "C" void kernel_launch(void* const* d_in, const int* in_sizes, int n_in,
                              void* d_out, int out_size) {
    const float* x       = (const float*)d_in[0];
    const float* weights = (const float*)d_in[1];
    const void*  in_idx  = d_in[2];
    const void*  out_idx = d_in[3];
    float* out = (float*)d_out;
    int E = in_sizes[1];
    if (E > EMAX) E = EMAX;

    cudaFuncSetAttribute(gemm_kernel,
                         cudaFuncAttributeMaxDynamicSharedMemorySize, SMEM_TOTAL);

    setup_kernel<<<1, 32>>>(in_idx, E);
    zero_w_kernel<<<(OUT_SIZE * IN_SIZE / 8) / 256, 256>>>();
    scatter_w_kernel<<<512, 256>>>(in_idx, out_idx, weights, E);
    convert_x_kernel<<<(BATCH * IN_SIZE / 4) / 256, 256>>>(x);

    dim3 grid(OUT_SIZE / 128, BATCH / 128);  // 16 x 8 = 128 CTAs
    gemm_kernel<<<grid, 256, SMEM_TOTAL>>>(out);
}

// round 8
// speedup vs baseline: 1.5714x; 1.5714x over previous
#include <cuda_runtime.h>
#include <cuda_fp16.h>
#include <stdint.h>

// Problem constants (fixed by the reference)
#define BATCH 1024
#define IN_SIZE 2048
#define OUT_SIZE 2048
#define EMAX 131072

#define BK 64                           // halves per K chunk (128B = SW128 row)
#define NCHUNKS (IN_SIZE / BK)          // 32
#define TILE_BYTES 16384                // 128 rows x 128 bytes
#define STAGE_BYTES (2 * TILE_BYTES)    // A tile + B tile
#define NSTAGES 3
#define SMEM_TOTAL (NSTAGES * STAGE_BYTES)   // 96 KB

// -------- device scratch (no allocations allowed) --------
__device__ __half g_Wh[OUT_SIZE * IN_SIZE];    // 8 MB dense weights fp16 [out][in]
__device__ __half g_xh[BATCH * IN_SIZE];       // 4 MB x fp16 [batch][in]
__device__ int    g_idx64;

__device__ __forceinline__ int fetch_idx(const void* p, int e, int is64) {
    if (is64) return (int)(((const long long*)p)[e]);
    return ((const int*)p)[e];
}

// ---------------- helpers ----------------
__device__ __forceinline__ uint32_t smem_u32(const void* p) {
    uint32_t a;
    asm("{ .reg .u64 t; cvta.to.shared.u64 t, %1; cvt.u32.u64 %0, t; }"
        : "=r"(a) : "l"(p));
    return a;
}
#define SWZ128(off) ((off) ^ (((off) >> 3) & 0x70))
#define CP_ASYNC16(dst, src) \
    asm volatile("cp.async.cg.shared.global [%0], [%1], 16;" :: "r"(dst), "l"(src))
#define CP_COMMIT() asm volatile("cp.async.commit_group;" ::: "memory")
#define CP_WAIT1()  asm volatile("cp.async.wait_group 1;" ::: "memory")
#define LDSM4(r0, r1, r2, r3, a)                                               \
    asm volatile("ldmatrix.sync.aligned.m8n8.x4.shared.b16 {%0,%1,%2,%3}, [%4];" \
                 : "=r"(r0), "=r"(r1), "=r"(r2), "=r"(r3) : "r"(a))
#define MMA16816(c, a, b0, b1)                                                 \
    asm volatile(                                                              \
        "mma.sync.aligned.m16n8k16.row.col.f32.f16.f16.f32 "                   \
        "{%0,%1,%2,%3}, {%4,%5,%6,%7}, {%8,%9}, {%0,%1,%2,%3};"                \
        : "+f"(c[0]), "+f"(c[1]), "+f"(c[2]), "+f"(c[3])                       \
        : "r"(a[0]), "r"(a[1]), "r"(a[2]), "r"(a[3]), "r"(b0), "r"(b1))

// -------- 1. prep: zero Wh + convert x + detect idx dtype (fused) -----------
// 2048 blocks x 256 thr. Thread id range covers both 512K-element vec arrays.
__global__ void __launch_bounds__(256) prep_kernel(const float* __restrict__ x,
                                                   const void* in_idx, int E) {
    int t = blockIdx.x * blockDim.x + threadIdx.x;

    // zero W: 4M halves = 512K uint4
    reinterpret_cast<uint4*>(g_Wh)[t] = make_uint4(0, 0, 0, 0);

    // convert x: 2M floats = 512K float4 -> 512K (half2,half2)
    float4 v = reinterpret_cast<const float4*>(x)[t];
    __half2 h0 = __floats2half2_rn(v.x, v.y);
    __half2 h1 = __floats2half2_rn(v.z, v.w);
    reinterpret_cast<__half2*>(g_xh)[2 * t]     = h0;
    reinterpret_cast<__half2*>(g_xh)[2 * t + 1] = h1;

    // dtype detection: block 0, warp 0
    if (blockIdx.x == 0 && threadIdx.x < 32) {
        int lane = threadIdx.x;
        const long long* q = (const long long*)in_idx;
        long long vv = (lane < E) ? q[lane] : 0;
        bool bad = (vv < 0 || vv >= IN_SIZE);
        unsigned m = __ballot_sync(0xFFFFFFFFu, bad);
        if (lane == 0) g_idx64 = (m == 0) ? 1 : 0;
    }
}

// -------- 2. scatter-add weights into dense fp16 W (spread f16x2 atomics) ---
__global__ void scatter_w_kernel(const void* in_idx, const void* out_idx,
                                 const float* w, int E) {
    int is64 = g_idx64;
    const __half zero = __float2half_rn(0.f);
    for (int e = blockIdx.x * blockDim.x + threadIdx.x; e < E;
         e += gridDim.x * blockDim.x) {
        int o = fetch_idx(out_idx, e, is64);
        int i = fetch_idx(in_idx, e, is64);
        int idx = o * IN_SIZE + i;
        __half hw = __float2half_rn(w[e]);
        __half2* p = reinterpret_cast<__half2*>(g_Wh + (idx & ~1));
        __half2 v = (idx & 1) ? __halves2half2(zero, hw)
                              : __halves2half2(hw, zero);
        atomicAdd(p, v);
    }
}

// -------- 3. GEMM: out[b][o] = sum_k xh[b][k] * Wh[o][k] --------------------
// CTA tile M128 x N128, 8 warps in 2x4 (64x32 per warp), BK=64, 3-stage
// cp.async pipeline, ldmatrix + mma.sync.m16n8k16 (HMMA, fp32 accum).
__global__ void __launch_bounds__(256, 1) gemm_kernel(float* __restrict__ out) {
    extern __shared__ char smem[];
    uint32_t sb = smem_u32(smem);
    int t = threadIdx.x;
    int wid = t >> 5;
    int lane = t & 31;
    int m0 = blockIdx.y << 7;   // batch tile origin
    int n0 = blockIdx.x << 7;   // out tile origin
    int wm = (wid & 1) << 6;    // warp m-origin within tile (0/64)
    int wn = (wid >> 1) << 5;   // warp n-origin within tile (0/32/64/96)

    const __half* axh = g_xh + (size_t)m0 * IN_SIZE;
    const __half* bwh = g_Wh + (size_t)n0 * IN_SIZE;

    // stage loader: chunk kc -> stage s. 2048 x 16B over 256 threads.
    auto load_tile = [&](int kc, int s) {
        uint32_t stage = sb + s * STAGE_BYTES;
        const __half* as = axh + kc * BK;
        const __half* bs = bwh + kc * BK;
#pragma unroll
        for (int q = t; q < 2048; q += 256) {
            int tile = q >> 10;           // 0=A, 1=B
            int r = (q >> 3) & 127;
            int sg = q & 7;
            uint32_t dst = stage + tile * TILE_BYTES + SWZ128((r << 7) + (sg << 4));
            const __half* src = (tile ? bs : as) + (size_t)r * IN_SIZE + sg * 8;
            CP_ASYNC16(dst, src);
        }
        CP_COMMIT();
    };

    float c[4][4][4];
#pragma unroll
    for (int a = 0; a < 4; a++)
#pragma unroll
        for (int b = 0; b < 4; b++)
#pragma unroll
            for (int k = 0; k < 4; k++) c[a][b][k] = 0.f;

    load_tile(0, 0);
    load_tile(1, 1);

    // per-lane ldmatrix address components (within-tile, pre-swizzle)
    int a_row = wm + (lane & 15);           // + mi*16
    int a_kh = (lane >> 4) << 3;            // + kk
    int b_row = wn + (lane & 7) + ((lane >> 4) << 3);  // + nj*16
    int b_kh = ((lane >> 3) & 1) << 3;      // + kk

    for (int ch = 0; ch < NCHUNKS; ch++) {
        CP_WAIT1();
        __syncthreads();
        uint32_t sA = sb + (ch % NSTAGES) * STAGE_BYTES;
        uint32_t sB = sA + TILE_BYTES;
#pragma unroll
        for (int kk = 0; kk < BK; kk += 16) {
            uint32_t af[4][4], bf[2][4];
#pragma unroll
            for (int mi = 0; mi < 4; mi++) {
                uint32_t ad = sA + SWZ128(((a_row + (mi << 4)) << 7) +
                                          ((kk + a_kh) << 1));
                LDSM4(af[mi][0], af[mi][1], af[mi][2], af[mi][3], ad);
            }
#pragma unroll
            for (int nj = 0; nj < 2; nj++) {
                uint32_t bd = sB + SWZ128(((b_row + (nj << 4)) << 7) +
                                          ((kk + b_kh) << 1));
                LDSM4(bf[nj][0], bf[nj][1], bf[nj][2], bf[nj][3], bd);
            }
#pragma unroll
            for (int mi = 0; mi < 4; mi++)
#pragma unroll
                for (int j = 0; j < 4; j++)
                    MMA16816(c[mi][j], af[mi],
                             bf[j >> 1][(j & 1) << 1],
                             bf[j >> 1][((j & 1) << 1) + 1]);
        }
        __syncthreads();
        if (ch + 2 < NCHUNKS) load_tile(ch + 2, (ch + 2) % NSTAGES);
    }

    // epilogue: write fp32 accumulators straight to d_out
    int rbase = m0 + wm + (lane >> 2);
    int cbase = n0 + wn + ((lane & 3) << 1);
#pragma unroll
    for (int mi = 0; mi < 4; mi++) {
#pragma unroll
        for (int j = 0; j < 4; j++) {
            int row = rbase + (mi << 4);
            int col = cbase + (j << 3);
            float* p0 = out + (size_t)row * OUT_SIZE + col;
            float* p1 = out + (size_t)(row + 8) * OUT_SIZE + col;
            p0[0] = c[mi][j][0]; p0[1] = c[mi][j][1];
            p1[0] = c[mi][j][2]; p1[1] = c[mi][j][3];
        }
    }
}

extern "C" void kernel_launch(void* const* d_in, const int* in_sizes, int n_in,
                              void* d_out, int out_size) {
    const float* x       = (const float*)d_in[0];
    const float* weights = (const float*)d_in[1];
    const void*  in_idx  = d_in[2];
    const void*  out_idx = d_in[3];
    float* out = (float*)d_out;
    int E = in_sizes[1];
    if (E > EMAX) E = EMAX;

    cudaFuncSetAttribute(gemm_kernel,
                         cudaFuncAttributeMaxDynamicSharedMemorySize, SMEM_TOTAL);

    // 1. fused prep: zero W (8 MB) + convert x (fp32->fp16) + dtype detect
    prep_kernel<<<2048, 256>>>(x, in_idx, E);

    // 2. scatter-add edge weights into dense fp16 W
    scatter_w_kernel<<<512, 256>>>(in_idx, out_idx, weights, E);

    // 3. tensor-core GEMM, epilogue writes d_out directly
    dim3 grid(OUT_SIZE / 128, BATCH / 128);  // 16 x 8 = 128 CTAs
    gemm_kernel<<<grid, 256, SMEM_TOTAL>>>(out);
}